// round 3
// baseline (speedup 1.0000x reference)
#include <cuda_runtime.h>
#include <cuda_bf16.h>
#include <cstdint>

#define NFEAT 256
#define NHID  128
#define MAXN  100000

// ---------------- scratch (no cudaMalloc allowed) ----------------
__device__ float g_z [MAXN * NHID];
__device__ float g_y1[MAXN * NHID];
__device__ float g_x1[MAXN * NHID];
__device__ float g_y2[MAXN * NHID];
__device__ int   g_rowptr[MAXN + 1];
__device__ __nv_bfloat16 g_Bc_hi[2 * NHID * NFEAT];  // [256 n][256 k]  (W_res|W1)^T
__device__ __nv_bfloat16 g_Bc_lo[2 * NHID * NFEAT];
__device__ __nv_bfloat16 g_B2_hi[NHID * NHID];       // [128 n][128 k]  W2^T
__device__ __nv_bfloat16 g_B2_lo[NHID * NHID];

__device__ __forceinline__ uint32_t pack_bf2(__nv_bfloat16 a, __nv_bfloat16 b) {
    return (uint32_t)__bfloat16_as_ushort(a) | ((uint32_t)__bfloat16_as_ushort(b) << 16);
}

// ---------------- weight prep: split + transpose ----------------
__global__ void prep_weights(const float* __restrict__ W_res, const float* __restrict__ W1,
                             const float* __restrict__ W2) {
    int idx = blockIdx.x * blockDim.x + threadIdx.x;
    if (idx < 2 * NHID * NFEAT) {
        int n = idx >> 8, k = idx & 255;
        float w = (n < NHID) ? W_res[k * NHID + n] : W1[k * NHID + (n - NHID)];
        __nv_bfloat16 h = __float2bfloat16(w);
        g_Bc_hi[n * NFEAT + k] = h;
        g_Bc_lo[n * NFEAT + k] = __float2bfloat16(w - __bfloat162float(h));
    } else {
        int j = idx - 2 * NHID * NFEAT;
        if (j < NHID * NHID) {
            int n = j >> 7, k = j & 127;
            float w = W2[k * NHID + n];
            __nv_bfloat16 h = __float2bfloat16(w);
            g_B2_hi[n * NHID + k] = h;
            g_B2_lo[n * NHID + k] = __float2bfloat16(w - __bfloat162float(h));
        }
    }
}

// ---------------- row_ptr: lower_bound on sorted edge_row ----------------
__global__ void build_rowptr(const int* __restrict__ edge_row, int n_edges, int n_nodes) {
    int i = blockIdx.x * blockDim.x + threadIdx.x;
    if (i > n_nodes) return;
    int lo = 0, hi = n_edges;
    while (lo < hi) {
        int mid = (lo + hi) >> 1;
        if (__ldg(edge_row + mid) < i) lo = mid + 1; else hi = mid;
    }
    g_rowptr[i] = lo;
}

// ---------------- split-bf16 mma.sync GEMM: C[M,128] = A[M,K] @ B^T ----------------
// A fp32 (converted to hi/lo bf16 on load), B pre-split bf16 [n][k].
// CTA tile 128x128, BK=32, 8 warps as 4(m) x 2(n) -> 32x64 warp tiles.
// mma.sync.m16n8k16.row.col, 3-term hi/lo compensation.

#define ASTRIDE 40   // bf16 elements per smem row (padded; 80 bytes)

__device__ __forceinline__ void mma16816(float c[4], const uint32_t a[4], const uint32_t b[2]) {
    asm volatile(
        "mma.sync.aligned.m16n8k16.row.col.f32.bf16.bf16.f32 "
        "{%0,%1,%2,%3}, {%4,%5,%6,%7}, {%8,%9}, {%0,%1,%2,%3};"
        : "+f"(c[0]), "+f"(c[1]), "+f"(c[2]), "+f"(c[3])
        : "r"(a[0]), "r"(a[1]), "r"(a[2]), "r"(a[3]), "r"(b[0]), "r"(b[1]));
}

__global__ void __launch_bounds__(256) gemm_split_bf16(
    const float* __restrict__ A, int lda, int Kfull, int n_rows,
    const __nv_bfloat16* __restrict__ Bhi, const __nv_bfloat16* __restrict__ Blo,
    float* __restrict__ C0, float* __restrict__ C1, const float* __restrict__ bias0)
{
    __shared__ __nv_bfloat16 Ah[128 * ASTRIDE];
    __shared__ __nv_bfloat16 Al[128 * ASTRIDE];
    __shared__ __nv_bfloat16 Bh[128 * ASTRIDE];
    __shared__ __nv_bfloat16 Bl[128 * ASTRIDE];

    const int tid = threadIdx.x, wid = tid >> 5, lane = tid & 31;
    const int g = lane >> 2, tig = lane & 3;     // groupID, thread-in-group
    const int warp_m = wid & 3, warp_n = wid >> 2;
    const int row0 = blockIdx.x * 128;
    const int n0g  = blockIdx.y * 128;           // B row offset in global
    float* C = (blockIdx.y == 0) ? C0 : C1;
    const float* bias = (blockIdx.y == 0) ? bias0 : nullptr;

    float acc[2][8][4];
    #pragma unroll
    for (int i = 0; i < 2; i++)
        #pragma unroll
        for (int j = 0; j < 8; j++)
            #pragma unroll
            for (int q = 0; q < 4; q++) acc[i][j][q] = 0.f;

    const int nchunks = Kfull >> 5;              // K chunks of 32
    for (int kc = 0; kc < nchunks; kc++) {
        // --- A tile: 128 rows x 32 cols fp32 -> hi/lo bf16 ---
        #pragma unroll
        for (int it = 0; it < 4; it++) {
            int idx = it * 256 + tid;            // 1024 float4 slots
            int r = idx >> 3, q = idx & 7;
            int grow = row0 + r;
            float4 v = make_float4(0.f, 0.f, 0.f, 0.f);
            if (grow < n_rows)
                v = *reinterpret_cast<const float4*>(A + (size_t)grow * lda + kc * 32 + q * 4);
            __nv_bfloat16 h0 = __float2bfloat16(v.x), h1 = __float2bfloat16(v.y);
            __nv_bfloat16 h2 = __float2bfloat16(v.z), h3 = __float2bfloat16(v.w);
            __nv_bfloat16 l0 = __float2bfloat16(v.x - __bfloat162float(h0));
            __nv_bfloat16 l1 = __float2bfloat16(v.y - __bfloat162float(h1));
            __nv_bfloat16 l2 = __float2bfloat16(v.z - __bfloat162float(h2));
            __nv_bfloat16 l3 = __float2bfloat16(v.w - __bfloat162float(h3));
            uint2* dh = reinterpret_cast<uint2*>(&Ah[r * ASTRIDE + q * 4]);
            uint2* dl = reinterpret_cast<uint2*>(&Al[r * ASTRIDE + q * 4]);
            *dh = make_uint2(pack_bf2(h0, h1), pack_bf2(h2, h3));
            *dl = make_uint2(pack_bf2(l0, l1), pack_bf2(l2, l3));
        }
        // --- B tile: 128 n-rows x 32 k bf16 (hi & lo) ---
        #pragma unroll
        for (int it = 0; it < 2; it++) {
            int idx = it * 256 + tid;            // 512 uint4 slots
            int r = idx >> 2, q = idx & 3;
            size_t src = (size_t)(n0g + r) * Kfull + kc * 32 + q * 8;
            *reinterpret_cast<uint4*>(&Bh[r * ASTRIDE + q * 8]) =
                *reinterpret_cast<const uint4*>(Bhi + src);
            *reinterpret_cast<uint4*>(&Bl[r * ASTRIDE + q * 8]) =
                *reinterpret_cast<const uint4*>(Blo + src);
        }
        __syncthreads();

        #pragma unroll
        for (int ks = 0; ks < 32; ks += 16) {
            uint32_t ah[2][4], al[2][4], bh[8][2], bl[8][2];
            #pragma unroll
            for (int mf = 0; mf < 2; mf++) {
                int rb = warp_m * 32 + mf * 16;
                int c0 = ks + tig * 2;
                ah[mf][0] = *reinterpret_cast<const uint32_t*>(&Ah[(rb + g)     * ASTRIDE + c0]);
                ah[mf][1] = *reinterpret_cast<const uint32_t*>(&Ah[(rb + g + 8) * ASTRIDE + c0]);
                ah[mf][2] = *reinterpret_cast<const uint32_t*>(&Ah[(rb + g)     * ASTRIDE + c0 + 8]);
                ah[mf][3] = *reinterpret_cast<const uint32_t*>(&Ah[(rb + g + 8) * ASTRIDE + c0 + 8]);
                al[mf][0] = *reinterpret_cast<const uint32_t*>(&Al[(rb + g)     * ASTRIDE + c0]);
                al[mf][1] = *reinterpret_cast<const uint32_t*>(&Al[(rb + g + 8) * ASTRIDE + c0]);
                al[mf][2] = *reinterpret_cast<const uint32_t*>(&Al[(rb + g)     * ASTRIDE + c0 + 8]);
                al[mf][3] = *reinterpret_cast<const uint32_t*>(&Al[(rb + g + 8) * ASTRIDE + c0 + 8]);
            }
            #pragma unroll
            for (int nf = 0; nf < 8; nf++) {
                int nr = warp_n * 64 + nf * 8 + g;
                int c0 = ks + tig * 2;
                bh[nf][0] = *reinterpret_cast<const uint32_t*>(&Bh[nr * ASTRIDE + c0]);
                bh[nf][1] = *reinterpret_cast<const uint32_t*>(&Bh[nr * ASTRIDE + c0 + 8]);
                bl[nf][0] = *reinterpret_cast<const uint32_t*>(&Bl[nr * ASTRIDE + c0]);
                bl[nf][1] = *reinterpret_cast<const uint32_t*>(&Bl[nr * ASTRIDE + c0 + 8]);
            }
            #pragma unroll
            for (int mf = 0; mf < 2; mf++)
                #pragma unroll
                for (int nf = 0; nf < 8; nf++) {
                    mma16816(acc[mf][nf], ah[mf], bh[nf]);
                    mma16816(acc[mf][nf], ah[mf], bl[nf]);
                    mma16816(acc[mf][nf], al[mf], bh[nf]);
                }
        }
        __syncthreads();
    }

    // ---- epilogue: write C (+bias) ----
    #pragma unroll
    for (int mf = 0; mf < 2; mf++) {
        int r_lo = row0 + warp_m * 32 + mf * 16 + g;
        int r_hi = r_lo + 8;
        #pragma unroll
        for (int nf = 0; nf < 8; nf++) {
            int col = warp_n * 64 + nf * 8 + tig * 2;
            float bx = 0.f, by = 0.f;
            if (bias) { bx = bias[col]; by = bias[col + 1]; }
            if (r_lo < n_rows) {
                float2 o = make_float2(acc[mf][nf][0] + bx, acc[mf][nf][1] + by);
                *reinterpret_cast<float2*>(C + (size_t)r_lo * NHID + col) = o;
            }
            if (r_hi < n_rows) {
                float2 o = make_float2(acc[mf][nf][2] + bx, acc[mf][nf][3] + by);
                *reinterpret_cast<float2*>(C + (size_t)r_hi * NHID + col) = o;
            }
        }
    }
}

// ---------------- SpMM #1 + relu + residual: x1 = relu(spmm(y1)+b1) + z ----------------
__global__ void spmm_relu_res(const int* __restrict__ col, const float* __restrict__ val,
                              const float* __restrict__ b1, int n) {
    int w = (blockIdx.x * blockDim.x + threadIdx.x) >> 5;
    int lane = threadIdx.x & 31;
    if (w >= n) return;
    int s = g_rowptr[w], e = g_rowptr[w + 1];
    const float4* src = reinterpret_cast<const float4*>(g_y1);
    float4 a0 = make_float4(0.f, 0.f, 0.f, 0.f), a1 = make_float4(0.f, 0.f, 0.f, 0.f);
    int i = s;
    for (; i + 1 < e; i += 2) {
        float v0 = __ldg(val + i),   v1 = __ldg(val + i + 1);
        int   c0 = __ldg(col + i),   c1 = __ldg(col + i + 1);
        float4 m0 = __ldg(src + (size_t)c0 * 32 + lane);
        float4 m1 = __ldg(src + (size_t)c1 * 32 + lane);
        a0.x += v0 * m0.x; a0.y += v0 * m0.y; a0.z += v0 * m0.z; a0.w += v0 * m0.w;
        a1.x += v1 * m1.x; a1.y += v1 * m1.y; a1.z += v1 * m1.z; a1.w += v1 * m1.w;
    }
    if (i < e) {
        float v = __ldg(val + i); int c = __ldg(col + i);
        float4 m = __ldg(src + (size_t)c * 32 + lane);
        a0.x += v * m.x; a0.y += v * m.y; a0.z += v * m.z; a0.w += v * m.w;
    }
    a0.x += a1.x; a0.y += a1.y; a0.z += a1.z; a0.w += a1.w;
    float4 bb = reinterpret_cast<const float4*>(b1)[lane];
    float4 zz = reinterpret_cast<const float4*>(g_z)[(size_t)w * 32 + lane];
    float4 r;
    r.x = fmaxf(a0.x + bb.x, 0.f) + zz.x;
    r.y = fmaxf(a0.y + bb.y, 0.f) + zz.y;
    r.z = fmaxf(a0.z + bb.z, 0.f) + zz.z;
    r.w = fmaxf(a0.w + bb.w, 0.f) + zz.w;
    reinterpret_cast<float4*>(g_x1)[(size_t)w * 32 + lane] = r;
}

// ---------------- SpMM #2 + bias + log_softmax ----------------
__global__ void spmm_logsoftmax(const int* __restrict__ col, const float* __restrict__ val,
                                const float* __restrict__ b2, float* __restrict__ out, int n) {
    int w = (blockIdx.x * blockDim.x + threadIdx.x) >> 5;
    int lane = threadIdx.x & 31;
    if (w >= n) return;
    int s = g_rowptr[w], e = g_rowptr[w + 1];
    const float4* src = reinterpret_cast<const float4*>(g_y2);
    float4 a0 = make_float4(0.f, 0.f, 0.f, 0.f), a1 = make_float4(0.f, 0.f, 0.f, 0.f);
    int i = s;
    for (; i + 1 < e; i += 2) {
        float v0 = __ldg(val + i),   v1 = __ldg(val + i + 1);
        int   c0 = __ldg(col + i),   c1 = __ldg(col + i + 1);
        float4 m0 = __ldg(src + (size_t)c0 * 32 + lane);
        float4 m1 = __ldg(src + (size_t)c1 * 32 + lane);
        a0.x += v0 * m0.x; a0.y += v0 * m0.y; a0.z += v0 * m0.z; a0.w += v0 * m0.w;
        a1.x += v1 * m1.x; a1.y += v1 * m1.y; a1.z += v1 * m1.z; a1.w += v1 * m1.w;
    }
    if (i < e) {
        float v = __ldg(val + i); int c = __ldg(col + i);
        float4 m = __ldg(src + (size_t)c * 32 + lane);
        a0.x += v * m.x; a0.y += v * m.y; a0.z += v * m.z; a0.w += v * m.w;
    }
    float4 bb = reinterpret_cast<const float4*>(b2)[lane];
    float4 h;
    h.x = a0.x + a1.x + bb.x; h.y = a0.y + a1.y + bb.y;
    h.z = a0.z + a1.z + bb.z; h.w = a0.w + a1.w + bb.w;
    float mx = fmaxf(fmaxf(h.x, h.y), fmaxf(h.z, h.w));
    #pragma unroll
    for (int o = 16; o > 0; o >>= 1) mx = fmaxf(mx, __shfl_xor_sync(0xffffffffu, mx, o));
    float sum = expf(h.x - mx) + expf(h.y - mx) + expf(h.z - mx) + expf(h.w - mx);
    #pragma unroll
    for (int o = 16; o > 0; o >>= 1) sum += __shfl_xor_sync(0xffffffffu, sum, o);
    float lse = mx + logf(sum);
    float4 r = make_float4(h.x - lse, h.y - lse, h.z - lse, h.w - lse);
    reinterpret_cast<float4*>(out)[(size_t)w * 32 + lane] = r;
}

// ---------------- launch ----------------
extern "C" void kernel_launch(void* const* d_in, const int* in_sizes, int n_in,
                              void* d_out, int out_size) {
    const float* x        = (const float*)d_in[0];
    const int*   edge_row = (const int*)  d_in[1];
    const int*   edge_col = (const int*)  d_in[2];
    const float* edge_val = (const float*)d_in[3];
    const float* W_res    = (const float*)d_in[4];
    const float* b_res    = (const float*)d_in[5];
    const float* W1       = (const float*)d_in[6];
    const float* b1       = (const float*)d_in[7];
    const float* W2       = (const float*)d_in[8];
    const float* b2       = (const float*)d_in[9];
    float* out = (float*)d_out;
    const int n_nodes = in_sizes[0] / NFEAT;
    const int n_edges = in_sizes[1];

    float *zp, *y1p, *x1p, *y2p;
    __nv_bfloat16 *bch, *bcl, *b2h, *b2l;
    cudaGetSymbolAddress((void**)&zp,  g_z);
    cudaGetSymbolAddress((void**)&y1p, g_y1);
    cudaGetSymbolAddress((void**)&x1p, g_x1);
    cudaGetSymbolAddress((void**)&y2p, g_y2);
    cudaGetSymbolAddress((void**)&bch, g_Bc_hi);
    cudaGetSymbolAddress((void**)&bcl, g_Bc_lo);
    cudaGetSymbolAddress((void**)&b2h, g_B2_hi);
    cudaGetSymbolAddress((void**)&b2l, g_B2_lo);

    prep_weights<<<(2 * NHID * NFEAT + NHID * NHID + 255) / 256, 256>>>(W_res, W1, W2);
    build_rowptr<<<(n_nodes + 1 + 255) / 256, 256>>>(edge_row, n_edges, n_nodes);

    // GEMM1: z = x@W_res + b_res (y==0), y1 = x@W1 (y==1); x converted on the fly
    dim3 g1((n_nodes + 127) / 128, 2);
    gemm_split_bf16<<<g1, 256>>>(x, NFEAT, NFEAT, n_nodes, bch, bcl, zp, y1p, b_res);

    // x1 = relu(spmm(y1)+b1) + z
    spmm_relu_res<<<(n_nodes * 32 + 255) / 256, 256>>>(edge_col, edge_val, b1, n_nodes);

    // GEMM2: y2 = x1 @ W2
    dim3 g2((n_nodes + 127) / 128, 1);
    gemm_split_bf16<<<g2, 256>>>(x1p, NHID, NHID, n_nodes, b2h, b2l, y2p, y2p, nullptr);

    // out = log_softmax(spmm(y2) + b2)
    spmm_logsoftmax<<<(n_nodes * 32 + 255) / 256, 256>>>(edge_col, edge_val, b2, out, n_nodes);
}

// round 4
// speedup vs baseline: 1.1369x; 1.1369x over previous
#include <cuda_runtime.h>
#include <cuda_bf16.h>
#include <cstdint>

#define NFEAT 256
#define NHID  128
#define MAXN  100000

// ---------------- scratch (no cudaMalloc allowed) ----------------
__device__ float g_z [MAXN * NHID];
__device__ float g_y1[MAXN * NHID];
__device__ float g_x1[MAXN * NHID];
__device__ float g_y2[MAXN * NHID];
__device__ int   g_rowptr[MAXN + 1];
__device__ __nv_bfloat16 g_Bc_hi[2 * NHID * NFEAT];  // [256 n][256 k]  (W_res|W1)^T
__device__ __nv_bfloat16 g_Bc_lo[2 * NHID * NFEAT];
__device__ __nv_bfloat16 g_B2_hi[NHID * NHID];       // [128 n][128 k]  W2^T
__device__ __nv_bfloat16 g_B2_lo[NHID * NHID];

__device__ __forceinline__ uint32_t pack_bf2(__nv_bfloat16 a, __nv_bfloat16 b) {
    return (uint32_t)__bfloat16_as_ushort(a) | ((uint32_t)__bfloat16_as_ushort(b) << 16);
}
__device__ __forceinline__ uint32_t smem_u32(const void* p) {
    uint32_t a;
    asm("{ .reg .u64 t; cvta.to.shared.u64 t, %1; cvt.u32.u64 %0, t; }" : "=r"(a) : "l"(p));
    return a;
}
__device__ __forceinline__ void ldsm_x4(uint32_t r[4], uint32_t saddr) {
    asm volatile("ldmatrix.sync.aligned.m8n8.x4.shared.b16 {%0,%1,%2,%3}, [%4];"
                 : "=r"(r[0]), "=r"(r[1]), "=r"(r[2]), "=r"(r[3]) : "r"(saddr));
}
__device__ __forceinline__ void cpa16(uint32_t dst, const void* src) {
    asm volatile("cp.async.cg.shared.global [%0], [%1], 16;" :: "r"(dst), "l"(src));
}
#define CP_COMMIT() asm volatile("cp.async.commit_group;" ::: "memory")
#define CP_WAIT0()  asm volatile("cp.async.wait_group 0;"  ::: "memory")

__device__ __forceinline__ void mma16816(float c[4], const uint32_t a[4], const uint32_t b[2]) {
    asm volatile(
        "mma.sync.aligned.m16n8k16.row.col.f32.bf16.bf16.f32 "
        "{%0,%1,%2,%3}, {%4,%5,%6,%7}, {%8,%9}, {%0,%1,%2,%3};"
        : "+f"(c[0]), "+f"(c[1]), "+f"(c[2]), "+f"(c[3])
        : "r"(a[0]), "r"(a[1]), "r"(a[2]), "r"(a[3]), "r"(b[0]), "r"(b[1]));
}

// ---------------- weight prep: split + transpose ----------------
__global__ void prep_weights(const float* __restrict__ W_res, const float* __restrict__ W1,
                             const float* __restrict__ W2) {
    int idx = blockIdx.x * blockDim.x + threadIdx.x;
    if (idx < 2 * NHID * NFEAT) {
        int n = idx >> 8, k = idx & 255;
        float w = (n < NHID) ? W_res[k * NHID + n] : W1[k * NHID + (n - NHID)];
        __nv_bfloat16 h = __float2bfloat16(w);
        g_Bc_hi[n * NFEAT + k] = h;
        g_Bc_lo[n * NFEAT + k] = __float2bfloat16(w - __bfloat162float(h));
    } else {
        int j = idx - 2 * NHID * NFEAT;
        if (j < NHID * NHID) {
            int n = j >> 7, k = j & 127;
            float w = W2[k * NHID + n];
            __nv_bfloat16 h = __float2bfloat16(w);
            g_B2_hi[n * NHID + k] = h;
            g_B2_lo[n * NHID + k] = __float2bfloat16(w - __bfloat162float(h));
        }
    }
}

// ---------------- row_ptr: lower_bound on sorted edge_row ----------------
__global__ void build_rowptr(const int* __restrict__ edge_row, int n_edges, int n_nodes) {
    int i = blockIdx.x * blockDim.x + threadIdx.x;
    if (i > n_nodes) return;
    int lo = 0, hi = n_edges;
    while (lo < hi) {
        int mid = (lo + hi) >> 1;
        if (__ldg(edge_row + mid) < i) lo = mid + 1; else hi = mid;
    }
    g_rowptr[i] = lo;
}

// ---------------- split-bf16 mma.sync GEMM, double-buffered + ldmatrix ----------------
// C[128 x NT] per CTA = A[128,K] @ B^T, 3-term hi/lo compensation.
// NT=256: cols 0..127 -> C0 (+bias0), cols 128..255 -> C1.  NT=128: all -> C0.
#define AS 40   // padded smem stride in bf16 elements (80B: ldmatrix conflict-free)

template <int NT>
__global__ void __launch_bounds__(256, 1) gemm_fused(
    const float* __restrict__ A, int lda, int Kfull, int n_rows,
    const __nv_bfloat16* __restrict__ Bhi, const __nv_bfloat16* __restrict__ Blo,
    float* __restrict__ C0, float* __restrict__ C1, const float* __restrict__ bias0)
{
    constexpr int NF = NT / 16;                       // n-fragments per warp
    constexpr uint32_t offAl = 128 * AS * 2;
    constexpr uint32_t offBh = 2 * 128 * AS * 2;
    constexpr uint32_t offBl = offBh + NT * AS * 2;
    constexpr uint32_t bufBytes = offBl + NT * AS * 2;

    extern __shared__ __nv_bfloat16 sm[];
    const uint32_t sbase = smem_u32(sm);

    const int tid = threadIdx.x, wid = tid >> 5, lane = tid & 31;
    const int g = lane >> 2, tig = lane & 3;
    const int warp_m = wid & 3, warp_n = wid >> 2;
    const int row0 = blockIdx.x * 128;

    float acc[2][NF][4];
    #pragma unroll
    for (int i = 0; i < 2; i++)
        #pragma unroll
        for (int j = 0; j < NF; j++)
            #pragma unroll
            for (int q = 0; q < 4; q++) acc[i][j][q] = 0.f;

    // ldmatrix per-lane offsets (element units)
    const int a_row = (lane & 7) + ((lane >> 3) & 1) * 8;   // + rb
    const int a_col = ((lane >> 4) & 1) * 8;                // + ks
    const int b_row = (lane & 7) + ((lane >> 4) & 1) * 8;   // + n0
    const int b_col = ((lane >> 3) & 1) * 8;                // + ks

    const int nchunks = Kfull >> 5;
    float4 va[4];

    auto loadA = [&](int kc) {
        #pragma unroll
        for (int it = 0; it < 4; it++) {
            int idx = it * 256 + tid;
            int r = idx >> 3, q = idx & 7;
            int grow = row0 + r;
            va[it] = make_float4(0.f, 0.f, 0.f, 0.f);
            if (grow < n_rows)
                va[it] = *reinterpret_cast<const float4*>(A + (size_t)grow * lda + kc * 32 + q * 4);
        }
    };
    auto storeA = [&](int buf) {
        __nv_bfloat16* Ahp = sm + (size_t)buf * (bufBytes / 2);
        __nv_bfloat16* Alp = Ahp + 128 * AS;
        #pragma unroll
        for (int it = 0; it < 4; it++) {
            int idx = it * 256 + tid;
            int r = idx >> 3, q = idx & 7;
            float4 v = va[it];
            __nv_bfloat16 h0 = __float2bfloat16(v.x), h1 = __float2bfloat16(v.y);
            __nv_bfloat16 h2 = __float2bfloat16(v.z), h3 = __float2bfloat16(v.w);
            __nv_bfloat16 l0 = __float2bfloat16(v.x - __bfloat162float(h0));
            __nv_bfloat16 l1 = __float2bfloat16(v.y - __bfloat162float(h1));
            __nv_bfloat16 l2 = __float2bfloat16(v.z - __bfloat162float(h2));
            __nv_bfloat16 l3 = __float2bfloat16(v.w - __bfloat162float(h3));
            *reinterpret_cast<uint2*>(&Ahp[r * AS + q * 4]) = make_uint2(pack_bf2(h0, h1), pack_bf2(h2, h3));
            *reinterpret_cast<uint2*>(&Alp[r * AS + q * 4]) = make_uint2(pack_bf2(l0, l1), pack_bf2(l2, l3));
        }
    };
    auto cpB = [&](int kc, int buf) {
        uint32_t bh = sbase + buf * bufBytes + offBh;
        uint32_t bl = sbase + buf * bufBytes + offBl;
        #pragma unroll
        for (int it = 0; it < NT / 64; it++) {
            int idx = it * 256 + tid;
            int r = idx >> 2, q = idx & 3;
            size_t src = (size_t)r * Kfull + kc * 32 + q * 8;
            uint32_t doff = (uint32_t)(r * AS + q * 8) * 2;
            cpa16(bh + doff, Bhi + src);
            cpa16(bl + doff, Blo + src);
        }
    };

    // prologue: chunk 0
    loadA(0);
    cpB(0, 0);
    CP_COMMIT();
    storeA(0);
    CP_WAIT0();
    __syncthreads();

    for (int kc = 0; kc < nchunks; kc++) {
        const int buf = kc & 1;
        const bool nb = (kc + 1 < nchunks);
        if (nb) { loadA(kc + 1); cpB(kc + 1, buf ^ 1); CP_COMMIT(); }

        const uint32_t aH = sbase + buf * bufBytes;
        const uint32_t aL = aH + offAl;
        const uint32_t bH = sbase + buf * bufBytes + offBh;
        const uint32_t bL = sbase + buf * bufBytes + offBl;

        #pragma unroll
        for (int ks = 0; ks < 32; ks += 16) {
            uint32_t ah[2][4], al[2][4];
            #pragma unroll
            for (int mf = 0; mf < 2; mf++) {
                int rb = warp_m * 32 + mf * 16;
                uint32_t ao = (uint32_t)((rb + a_row) * AS + ks + a_col) * 2;
                ldsm_x4(ah[mf], aH + ao);
                ldsm_x4(al[mf], aL + ao);
            }
            #pragma unroll
            for (int p = 0; p < NF / 2; p++) {
                int n0 = warp_n * (NT / 2) + p * 16;
                uint32_t bo = (uint32_t)((n0 + b_row) * AS + ks + b_col) * 2;
                uint32_t bh4[4], bl4[4];
                ldsm_x4(bh4, bH + bo);
                ldsm_x4(bl4, bL + bo);
                #pragma unroll
                for (int mf = 0; mf < 2; mf++) {
                    mma16816(acc[mf][2 * p],     ah[mf], &bh4[0]);
                    mma16816(acc[mf][2 * p],     ah[mf], &bl4[0]);
                    mma16816(acc[mf][2 * p],     al[mf], &bh4[0]);
                    mma16816(acc[mf][2 * p + 1], ah[mf], &bh4[2]);
                    mma16816(acc[mf][2 * p + 1], ah[mf], &bl4[2]);
                    mma16816(acc[mf][2 * p + 1], al[mf], &bh4[2]);
                }
            }
        }

        if (nb) { storeA(buf ^ 1); CP_WAIT0(); }
        __syncthreads();
    }

    // ---- epilogue ----
    float* dest = (NT == 256) ? (warp_n ? C1 : C0) : C0;
    const float* bias = (NT == 256 && warp_n == 0) ? bias0 : nullptr;
    const int colbase = (NT == 256) ? 0 : warp_n * 64;

    #pragma unroll
    for (int mf = 0; mf < 2; mf++) {
        int r_lo = row0 + warp_m * 32 + mf * 16 + g;
        int r_hi = r_lo + 8;
        #pragma unroll
        for (int nf = 0; nf < NF; nf++) {
            int col = colbase + nf * 8 + tig * 2;
            float bx = 0.f, by = 0.f;
            if (bias) { bx = bias[col]; by = bias[col + 1]; }
            if (r_lo < n_rows) {
                float2 o = make_float2(acc[mf][nf][0] + bx, acc[mf][nf][1] + by);
                *reinterpret_cast<float2*>(dest + (size_t)r_lo * NHID + col) = o;
            }
            if (r_hi < n_rows) {
                float2 o = make_float2(acc[mf][nf][2] + bx, acc[mf][nf][3] + by);
                *reinterpret_cast<float2*>(dest + (size_t)r_hi * NHID + col) = o;
            }
        }
    }
}

// ---------------- SpMM #1 + relu + residual: x1 = relu(spmm(y1)+b1) + z ----------------
__global__ void spmm_relu_res(const int* __restrict__ col, const float* __restrict__ val,
                              const float* __restrict__ b1, int n) {
    int w = (blockIdx.x * blockDim.x + threadIdx.x) >> 5;
    int lane = threadIdx.x & 31;
    if (w >= n) return;
    int s = g_rowptr[w], e = g_rowptr[w + 1];
    const float4* src = reinterpret_cast<const float4*>(g_y1);
    float4 a0 = make_float4(0.f,0.f,0.f,0.f), a1 = a0, a2 = a0, a3 = a0;
    int i = s;
    for (; i + 3 < e; i += 4) {
        float v0 = __ldg(val + i),     v1 = __ldg(val + i + 1);
        float v2 = __ldg(val + i + 2), v3 = __ldg(val + i + 3);
        int c0 = __ldg(col + i),     c1 = __ldg(col + i + 1);
        int c2 = __ldg(col + i + 2), c3 = __ldg(col + i + 3);
        float4 m0 = __ldg(src + (size_t)c0 * 32 + lane);
        float4 m1 = __ldg(src + (size_t)c1 * 32 + lane);
        float4 m2 = __ldg(src + (size_t)c2 * 32 + lane);
        float4 m3 = __ldg(src + (size_t)c3 * 32 + lane);
        a0.x += v0*m0.x; a0.y += v0*m0.y; a0.z += v0*m0.z; a0.w += v0*m0.w;
        a1.x += v1*m1.x; a1.y += v1*m1.y; a1.z += v1*m1.z; a1.w += v1*m1.w;
        a2.x += v2*m2.x; a2.y += v2*m2.y; a2.z += v2*m2.z; a2.w += v2*m2.w;
        a3.x += v3*m3.x; a3.y += v3*m3.y; a3.z += v3*m3.z; a3.w += v3*m3.w;
    }
    if (i + 1 < e) {
        float v0 = __ldg(val + i), v1 = __ldg(val + i + 1);
        int c0 = __ldg(col + i), c1 = __ldg(col + i + 1);
        float4 m0 = __ldg(src + (size_t)c0 * 32 + lane);
        float4 m1 = __ldg(src + (size_t)c1 * 32 + lane);
        a0.x += v0*m0.x; a0.y += v0*m0.y; a0.z += v0*m0.z; a0.w += v0*m0.w;
        a1.x += v1*m1.x; a1.y += v1*m1.y; a1.z += v1*m1.z; a1.w += v1*m1.w;
        i += 2;
    }
    if (i < e) {
        float v = __ldg(val + i); int c = __ldg(col + i);
        float4 m = __ldg(src + (size_t)c * 32 + lane);
        a2.x += v*m.x; a2.y += v*m.y; a2.z += v*m.z; a2.w += v*m.w;
    }
    a0.x += a1.x + a2.x + a3.x; a0.y += a1.y + a2.y + a3.y;
    a0.z += a1.z + a2.z + a3.z; a0.w += a1.w + a2.w + a3.w;
    float4 bb = reinterpret_cast<const float4*>(b1)[lane];
    float4 zz = reinterpret_cast<const float4*>(g_z)[(size_t)w * 32 + lane];
    float4 r;
    r.x = fmaxf(a0.x + bb.x, 0.f) + zz.x;
    r.y = fmaxf(a0.y + bb.y, 0.f) + zz.y;
    r.z = fmaxf(a0.z + bb.z, 0.f) + zz.z;
    r.w = fmaxf(a0.w + bb.w, 0.f) + zz.w;
    reinterpret_cast<float4*>(g_x1)[(size_t)w * 32 + lane] = r;
}

// ---------------- SpMM #2 + bias + log_softmax ----------------
__global__ void spmm_logsoftmax(const int* __restrict__ col, const float* __restrict__ val,
                                const float* __restrict__ b2, float* __restrict__ out, int n) {
    int w = (blockIdx.x * blockDim.x + threadIdx.x) >> 5;
    int lane = threadIdx.x & 31;
    if (w >= n) return;
    int s = g_rowptr[w], e = g_rowptr[w + 1];
    const float4* src = reinterpret_cast<const float4*>(g_y2);
    float4 a0 = make_float4(0.f,0.f,0.f,0.f), a1 = a0, a2 = a0, a3 = a0;
    int i = s;
    for (; i + 3 < e; i += 4) {
        float v0 = __ldg(val + i),     v1 = __ldg(val + i + 1);
        float v2 = __ldg(val + i + 2), v3 = __ldg(val + i + 3);
        int c0 = __ldg(col + i),     c1 = __ldg(col + i + 1);
        int c2 = __ldg(col + i + 2), c3 = __ldg(col + i + 3);
        float4 m0 = __ldg(src + (size_t)c0 * 32 + lane);
        float4 m1 = __ldg(src + (size_t)c1 * 32 + lane);
        float4 m2 = __ldg(src + (size_t)c2 * 32 + lane);
        float4 m3 = __ldg(src + (size_t)c3 * 32 + lane);
        a0.x += v0*m0.x; a0.y += v0*m0.y; a0.z += v0*m0.z; a0.w += v0*m0.w;
        a1.x += v1*m1.x; a1.y += v1*m1.y; a1.z += v1*m1.z; a1.w += v1*m1.w;
        a2.x += v2*m2.x; a2.y += v2*m2.y; a2.z += v2*m2.z; a2.w += v2*m2.w;
        a3.x += v3*m3.x; a3.y += v3*m3.y; a3.z += v3*m3.z; a3.w += v3*m3.w;
    }
    if (i + 1 < e) {
        float v0 = __ldg(val + i), v1 = __ldg(val + i + 1);
        int c0 = __ldg(col + i), c1 = __ldg(col + i + 1);
        float4 m0 = __ldg(src + (size_t)c0 * 32 + lane);
        float4 m1 = __ldg(src + (size_t)c1 * 32 + lane);
        a0.x += v0*m0.x; a0.y += v0*m0.y; a0.z += v0*m0.z; a0.w += v0*m0.w;
        a1.x += v1*m1.x; a1.y += v1*m1.y; a1.z += v1*m1.z; a1.w += v1*m1.w;
        i += 2;
    }
    if (i < e) {
        float v = __ldg(val + i); int c = __ldg(col + i);
        float4 m = __ldg(src + (size_t)c * 32 + lane);
        a2.x += v*m.x; a2.y += v*m.y; a2.z += v*m.z; a2.w += v*m.w;
    }
    float4 bb = reinterpret_cast<const float4*>(b2)[lane];
    float4 h;
    h.x = a0.x + a1.x + a2.x + a3.x + bb.x;
    h.y = a0.y + a1.y + a2.y + a3.y + bb.y;
    h.z = a0.z + a1.z + a2.z + a3.z + bb.z;
    h.w = a0.w + a1.w + a2.w + a3.w + bb.w;
    float mx = fmaxf(fmaxf(h.x, h.y), fmaxf(h.z, h.w));
    #pragma unroll
    for (int o = 16; o > 0; o >>= 1) mx = fmaxf(mx, __shfl_xor_sync(0xffffffffu, mx, o));
    float sum = expf(h.x - mx) + expf(h.y - mx) + expf(h.z - mx) + expf(h.w - mx);
    #pragma unroll
    for (int o = 16; o > 0; o >>= 1) sum += __shfl_xor_sync(0xffffffffu, sum, o);
    float lse = mx + logf(sum);
    float4 r = make_float4(h.x - lse, h.y - lse, h.z - lse, h.w - lse);
    reinterpret_cast<float4*>(out)[(size_t)w * 32 + lane] = r;
}

// ---------------- launch ----------------
extern "C" void kernel_launch(void* const* d_in, const int* in_sizes, int n_in,
                              void* d_out, int out_size) {
    const float* x        = (const float*)d_in[0];
    const int*   edge_row = (const int*)  d_in[1];
    const int*   edge_col = (const int*)  d_in[2];
    const float* edge_val = (const float*)d_in[3];
    const float* W_res    = (const float*)d_in[4];
    const float* b_res    = (const float*)d_in[5];
    const float* W1       = (const float*)d_in[6];
    const float* b1       = (const float*)d_in[7];
    const float* W2       = (const float*)d_in[8];
    const float* b2       = (const float*)d_in[9];
    float* out = (float*)d_out;
    const int n_nodes = in_sizes[0] / NFEAT;
    const int n_edges = in_sizes[1];

    float *zp, *y1p, *x1p, *y2p;
    __nv_bfloat16 *bch, *bcl, *b2h, *b2l;
    cudaGetSymbolAddress((void**)&zp,  g_z);
    cudaGetSymbolAddress((void**)&y1p, g_y1);
    cudaGetSymbolAddress((void**)&x1p, g_x1);
    cudaGetSymbolAddress((void**)&y2p, g_y2);
    cudaGetSymbolAddress((void**)&bch, g_Bc_hi);
    cudaGetSymbolAddress((void**)&bcl, g_Bc_lo);
    cudaGetSymbolAddress((void**)&b2h, g_B2_hi);
    cudaGetSymbolAddress((void**)&b2l, g_B2_lo);

    // dyn smem: 2 buffers of (2*128 + 2*NT) rows * 40 el * 2B
    const int smem256 = 2 * (2 * 128 + 2 * 256) * AS * 2;  // 122880
    const int smem128 = 2 * (2 * 128 + 2 * 128) * AS * 2;  // 81920
    cudaFuncSetAttribute(gemm_fused<256>, cudaFuncAttributeMaxDynamicSharedMemorySize, smem256);
    cudaFuncSetAttribute(gemm_fused<128>, cudaFuncAttributeMaxDynamicSharedMemorySize, smem128);

    prep_weights<<<(2 * NHID * NFEAT + NHID * NHID + 255) / 256, 256>>>(W_res, W1, W2);
    build_rowptr<<<(n_nodes + 1 + 255) / 256, 256>>>(edge_row, n_edges, n_nodes);

    const int gx = (n_nodes + 127) / 128;
    // GEMM1 (fused N=256): z = x@W_res + b_res, y1 = x@W1
    gemm_fused<256><<<gx, 256, smem256>>>(x, NFEAT, NFEAT, n_nodes, bch, bcl, zp, y1p, b_res);

    // x1 = relu(spmm(y1)+b1) + z
    spmm_relu_res<<<(n_nodes * 32 + 255) / 256, 256>>>(edge_col, edge_val, b1, n_nodes);

    // GEMM2: y2 = x1 @ W2
    gemm_fused<128><<<gx, 256, smem128>>>(x1p, NHID, NHID, n_nodes, b2h, b2l, y2p, nullptr, nullptr);

    // out = log_softmax(spmm(y2) + b2)
    spmm_logsoftmax<<<(n_nodes * 32 + 255) / 256, 256>>>(edge_col, edge_val, b2, out, n_nodes);
}